// round 7
// baseline (speedup 1.0000x reference)
#include <cuda_runtime.h>
#include <cuda_fp16.h>
#include <cstdint>
#include <cstddef>

#define BATCH     131072
#define FDIM      512
#define F2DIM     256
#define OBJ_DIM   100000
#define PRED_DIM  2000
#define EPS_F     1e-5f

// ---------------- device scratch (static, no allocation) ----------------
__device__ int   d_cnt_s[OBJ_DIM];
__device__ int   d_cnt_o[OBJ_DIM];
__device__ int   d_cnt_p[PRED_DIM + 8];
__device__ __align__(16) float d_sumb[3][FDIM];
__device__ __align__(16) float d_sqb [3][FDIM];
__device__ __align__(16) __half d_W4h[F2DIM * FDIM];         // fp16 W4, row-major [256][512]
__device__ __align__(16) __half d_yh[(size_t)BATCH * F2DIM]; // pre-BN layer-4 out, fp16, 64 MB
__device__ float d_sum4[F2DIM];
__device__ float d_sq4 [F2DIM];

// ---------------- helpers ----------------
__device__ __forceinline__ uint32_t smem_u32(const void* p) {
    uint32_t a;
    asm("{ .reg .u64 t; cvta.to.shared.u64 t, %1; cvt.u32.u64 %0, t; }" : "=r"(a) : "l"(p));
    return a;
}
__device__ __forceinline__ void cp16(uint32_t dst, const void* src) {
    asm volatile("cp.async.cg.shared.global [%0], [%1], 16;" :: "r"(dst), "l"(src) : "memory");
}
__device__ __forceinline__ void cp_commit() {
    asm volatile("cp.async.commit_group;" ::: "memory");
}
__device__ __forceinline__ float relu_aff(float a, float w, float c) {
    return fmaxf(fmaf(a, w, c), 0.f);
}

// ---------------- kernel 0: zero scratch + W4 -> fp16 ----------------
__global__ void __launch_bounds__(256) k_zero(const float* __restrict__ W4) {
    int i = blockIdx.x * blockDim.x + threadIdx.x;   // grid 512*256 = 131072
    if (i < OBJ_DIM) { d_cnt_s[i] = 0; d_cnt_o[i] = 0; }
    if (i < PRED_DIM + 8) d_cnt_p[i] = 0;
    if (i < FDIM) {
        #pragma unroll
        for (int b = 0; b < 3; b++) { d_sumb[b][i] = 0.f; d_sqb[b][i] = 0.f; }
    }
    if (i < F2DIM) { d_sum4[i] = 0.f; d_sq4[i] = 0.f; }
    d_W4h[i] = __float2half_rn(W4[i]);
}

// ---------------- kernel 1: index histograms ----------------
__global__ void k_hist(const int* __restrict__ subj, const int* __restrict__ obj,
                       const int* __restrict__ predi) {
    int i = blockIdx.x * blockDim.x + threadIdx.x;
    if (i < BATCH) {
        atomicAdd(&d_cnt_s[subj[i]], 1);
        atomicAdd(&d_cnt_o[obj[i]], 1);
        atomicAdd(&d_cnt_p[predi[i]], 1);
    }
}

// ---------------- kernel 2: count-weighted column stats (counts read inline) ----------------
__global__ void __launch_bounds__(128) k_cs(const float* __restrict__ W1,
                                            const float* __restrict__ W2,
                                            const float* __restrict__ W3,
                                            int S1, int S2) {
    const float* W; const int* cnt; int sel, bid, nblk, R;
    if ((int)blockIdx.x < S1)      { W = W1; cnt = d_cnt_s; sel = 0; bid = blockIdx.x;      nblk = S1;             R = OBJ_DIM; }
    else if ((int)blockIdx.x < S2) { W = W2; cnt = d_cnt_o; sel = 1; bid = blockIdx.x - S1; nblk = S2 - S1;        R = OBJ_DIM; }
    else                           { W = W3; cnt = d_cnt_p; sel = 2; bid = blockIdx.x - S2; nblk = gridDim.x - S2; R = PRED_DIM; }
    const int t = threadIdx.x;
    float4 s = make_float4(0.f, 0.f, 0.f, 0.f);
    float4 q = make_float4(0.f, 0.f, 0.f, 0.f);
    for (int base = bid * 8; base < R; base += nblk * 8) {
        int4 ca = *(const int4*)(cnt + base);
        int4 cb = *(const int4*)(cnt + base + 4);
        int cc[8] = {ca.x, ca.y, ca.z, ca.w, cb.x, cb.y, cb.z, cb.w};
        float4 v[8];
        #pragma unroll
        for (int u = 0; u < 8; u++)
            if (cc[u]) v[u] = __ldg((const float4*)(W + (size_t)(base + u) * FDIM) + t);
        #pragma unroll
        for (int u = 0; u < 8; u++) {
            if (cc[u]) {
                float fc = (float)cc[u];
                s.x += fc * v[u].x; s.y += fc * v[u].y; s.z += fc * v[u].z; s.w += fc * v[u].w;
                q.x += fc * v[u].x * v[u].x; q.y += fc * v[u].y * v[u].y;
                q.z += fc * v[u].z * v[u].z; q.w += fc * v[u].w * v[u].w;
            }
        }
    }
    int c0 = t * 4;
    atomicAdd(&d_sumb[sel][c0 + 0], s.x);
    atomicAdd(&d_sumb[sel][c0 + 1], s.y);
    atomicAdd(&d_sumb[sel][c0 + 2], s.z);
    atomicAdd(&d_sumb[sel][c0 + 3], s.w);
    atomicAdd(&d_sqb[sel][c0 + 0], q.x);
    atomicAdd(&d_sqb[sel][c0 + 1], q.y);
    atomicAdd(&d_sqb[sel][c0 + 2], q.z);
    atomicAdd(&d_sqb[sel][c0 + 3], q.w);
}

// ---------------- kernel 3: FUSED gather + BN-relu + GEMM + stats ----------------
// 128 rows/block, 512 threads. A tile lives only in smem.
// SMEM map (bytes):
//   [0, 133120)           A tile: 128 rows x 520 halfs (1040 B/row, bank-shift 4)
//   [133120, 206848)      shared: gather ring (3 x 24576) THEN B double-buffer (2 x 36864)
//   [206848, 219136)      cA[3*512], cC[3*512]
//   [219136, 220672)      idx[3*128]
//   [220672, 222720)      colsum[256], colsq[256]
#define F_ROWS   128
#define A_STRIDE 520
#define SM_SHR   133120
#define STG_B    24576
#define B_ST     36864
#define SM_COEF  206848
#define SM_IDX   219136
#define SM_SUM   220672
#define SM_SQ    221696
#define SM_TOT   222720

__global__ void __launch_bounds__(512, 1) k_fused(
    const int* __restrict__ subj, const int* __restrict__ obj, const int* __restrict__ predi,
    const float* __restrict__ W1, const float* __restrict__ W2, const float* __restrict__ W3,
    const float* __restrict__ g1, const float* __restrict__ be1,
    const float* __restrict__ g2, const float* __restrict__ be2,
    const float* __restrict__ g3, const float* __restrict__ be3)
{
    extern __shared__ char sm[];
    const uint32_t smb = smem_u32(sm);
    __half* A = (__half*)sm;
    float* cA = (float*)(sm + SM_COEF);
    float* cC = (float*)(sm + SM_COEF + 6144);
    int*   idxs = (int*)(sm + SM_IDX);
    float* colsum = (float*)(sm + SM_SUM);
    float* colsq  = (float*)(sm + SM_SQ);
    const int tid = threadIdx.x, lane = tid & 31, wid = tid >> 5;
    const int i0 = blockIdx.x * F_ROWS;

    if (tid < F_ROWS) {
        idxs[tid]       = subj[i0 + tid];
        idxs[128 + tid] = obj[i0 + tid];
        idxs[256 + tid] = predi[i0 + tid];
    }
    if (tid < 256) { colsum[tid] = 0.f; colsq[tid] = 0.f; }
    for (int t = tid; t < FDIM; t += 512) {
        float m, v, a;
        m = d_sumb[0][t] * (1.f / BATCH); v = d_sqb[0][t] * (1.f / BATCH) - m * m;
        a = g1[t] * rsqrtf(v + EPS_F); cA[t] = a;          cC[t] = be1[t] - a * m;
        m = d_sumb[1][t] * (1.f / BATCH); v = d_sqb[1][t] * (1.f / BATCH) - m * m;
        a = g2[t] * rsqrtf(v + EPS_F); cA[512 + t] = a;    cC[512 + t] = be2[t] - a * m;
        m = d_sumb[2][t] * (1.f / BATCH); v = d_sqb[2][t] * (1.f / BATCH) - m * m;
        a = g3[t] * rsqrtf(v + EPS_F); cA[1024 + t] = a;   cC[1024 + t] = be3[t] - a * m;
    }
    __syncthreads();

    // ===== phase 1: gather -> BN-relu-sum -> fp16 A tile =====
    // 32 stages of 4 rows; 3-stage ring in the shared region.
    const int c4  = tid & 127;        // colgroup (float4 id)
    const int ris = tid >> 7;         // row in stage 0..3
    const int k0  = c4 * 4;
    const float4 A1 = *(const float4*)&cA[k0],        C1 = *(const float4*)&cC[k0];
    const float4 A2 = *(const float4*)&cA[512 + k0],  C2 = *(const float4*)&cC[512 + k0];
    const float4 A3 = *(const float4*)&cA[1024 + k0], C3 = *(const float4*)&cC[1024 + k0];

    auto issue = [&](int s) {
        uint32_t dstb = smb + SM_SHR + (s % 3) * STG_B;
        #pragma unroll
        for (int u = 0; u < 3; u++) {
            int lin = tid + 512 * u;            // 0..1535 float4 slots
            int rr  = lin / 384;                // row in stage
            int rem = lin - rr * 384;
            int tab = rem >> 7;                 // table 0..2
            int cc  = rem & 127;                // float4 col
            int gi  = idxs[tab * 128 + s * 4 + rr];
            const float* Wt = (tab == 0) ? W1 : (tab == 1) ? W2 : W3;
            cp16(dstb + lin * 16, Wt + (size_t)gi * FDIM + cc * 4);
        }
        cp_commit();
    };

    issue(0); issue(1);
    #pragma unroll 1
    for (int s = 0; s < 32; s++) {
        if (s + 2 < 32) issue(s + 2);
        if (s < 30)       asm volatile("cp.async.wait_group 2;" ::: "memory");
        else if (s == 30) asm volatile("cp.async.wait_group 1;" ::: "memory");
        else              asm volatile("cp.async.wait_group 0;" ::: "memory");
        __syncthreads();
        const float4* st4 = (const float4*)(sm + SM_SHR + (s % 3) * STG_B);
        float4 w1 = st4[ris * 384 + c4];
        float4 w2 = st4[ris * 384 + 128 + c4];
        float4 w3 = st4[ris * 384 + 256 + c4];
        float f0 = relu_aff(A1.x, w1.x, C1.x) + relu_aff(A2.x, w2.x, C2.x) + relu_aff(A3.x, w3.x, C3.x);
        float f1 = relu_aff(A1.y, w1.y, C1.y) + relu_aff(A2.y, w2.y, C2.y) + relu_aff(A3.y, w3.y, C3.y);
        float f2 = relu_aff(A1.z, w1.z, C1.z) + relu_aff(A2.z, w2.z, C2.z) + relu_aff(A3.z, w3.z, C3.z);
        float f3 = relu_aff(A1.w, w1.w, C1.w) + relu_aff(A2.w, w2.w, C2.w) + relu_aff(A3.w, w3.w, C3.w);
        __half2 h0 = __floats2half2_rn(f0, f1);
        __half2 h1 = __floats2half2_rn(f2, f3);
        uint2 u;
        u.x = *(unsigned*)&h0;
        u.y = *(unsigned*)&h1;
        *(uint2*)(A + (s * 4 + ris) * A_STRIDE + k0) = u;
        __syncthreads();
    }

    // ===== phase 2: GEMM y[128x256] = A[128x512] @ W4h^T, B double-buffered =====
    const int wm = wid >> 2, wn = wid & 3, g = lane >> 2, tig = lane & 3;

    auto issueB = [&](int c) {
        uint32_t dstb = smb + SM_SHR + (c & 1) * B_ST;
        #pragma unroll
        for (int u = 0; u < 4; u++) {
            int idx = tid + 512 * u;            // 0..2047
            int n = idx >> 3, o = idx & 7;
            cp16(dstb + n * 144 + o * 16, d_W4h + n * FDIM + c * 64 + o * 8);
        }
        cp_commit();
    };

    float acc[2][8][4];
    #pragma unroll
    for (int mt = 0; mt < 2; mt++)
        #pragma unroll
        for (int nt = 0; nt < 8; nt++)
            #pragma unroll
            for (int u = 0; u < 4; u++) acc[mt][nt][u] = 0.f;

    issueB(0);
    #pragma unroll 1
    for (int c = 0; c < 8; c++) {
        if (c < 7) {
            issueB(c + 1);
            asm volatile("cp.async.wait_group 1;" ::: "memory");
        } else {
            asm volatile("cp.async.wait_group 0;" ::: "memory");
        }
        __syncthreads();
        const char* Bbase = sm + SM_SHR + (c & 1) * B_ST;
        #pragma unroll
        for (int ki = 0; ki < 4; ki++) {
            const int ks = ki * 16;
            unsigned a[2][4];
            #pragma unroll
            for (int mt = 0; mt < 2; mt++) {
                const __half* ap = A + (wm * 32 + mt * 16 + g) * A_STRIDE + c * 64 + ks + tig * 2;
                a[mt][0] = *(const unsigned*)(ap);
                a[mt][1] = *(const unsigned*)(ap + 8 * A_STRIDE);
                a[mt][2] = *(const unsigned*)(ap + 8);
                a[mt][3] = *(const unsigned*)(ap + 8 * A_STRIDE + 8);
            }
            #pragma unroll
            for (int nt = 0; nt < 8; nt++) {
                int n = wn * 64 + nt * 8 + g;
                const __half* bp = (const __half*)(Bbase + n * 144) + ks + tig * 2;
                unsigned b0 = *(const unsigned*)(bp);
                unsigned b1 = *(const unsigned*)(bp + 8);
                #pragma unroll
                for (int mt = 0; mt < 2; mt++) {
                    asm volatile(
                        "mma.sync.aligned.m16n8k16.row.col.f32.f16.f16.f32 "
                        "{%0,%1,%2,%3}, {%4,%5,%6,%7}, {%8,%9}, {%0,%1,%2,%3};\n"
                        : "+f"(acc[mt][nt][0]), "+f"(acc[mt][nt][1]),
                          "+f"(acc[mt][nt][2]), "+f"(acc[mt][nt][3])
                        : "r"(a[mt][0]), "r"(a[mt][1]), "r"(a[mt][2]), "r"(a[mt][3]),
                          "r"(b0), "r"(b1));
                }
            }
        }
        __syncthreads();
    }

    // ===== epilogue: store y (fp16) + column sum/sumsq (fp32 from accs) =====
    #pragma unroll
    for (int nt = 0; nt < 8; nt++) {
        int col = wn * 64 + nt * 8 + tig * 2;
        float s0 = 0.f, s1 = 0.f, q0 = 0.f, q1 = 0.f;
        #pragma unroll
        for (int mt = 0; mt < 2; mt++) {
            float c0 = acc[mt][nt][0], c1 = acc[mt][nt][1];
            float c2 = acc[mt][nt][2], c3 = acc[mt][nt][3];
            int r = i0 + wm * 32 + mt * 16 + g;
            *(__half2*)(d_yh + (size_t)r * F2DIM + col)       = __floats2half2_rn(c0, c1);
            *(__half2*)(d_yh + (size_t)(r + 8) * F2DIM + col) = __floats2half2_rn(c2, c3);
            s0 += c0 + c2;  s1 += c1 + c3;
            q0 += c0 * c0 + c2 * c2;  q1 += c1 * c1 + c3 * c3;
        }
        #pragma unroll
        for (int off = 4; off < 32; off <<= 1) {
            s0 += __shfl_xor_sync(0xffffffffu, s0, off);
            s1 += __shfl_xor_sync(0xffffffffu, s1, off);
            q0 += __shfl_xor_sync(0xffffffffu, q0, off);
            q1 += __shfl_xor_sync(0xffffffffu, q1, off);
        }
        if (lane < 4) {
            atomicAdd(&colsum[col], s0);
            atomicAdd(&colsum[col + 1], s1);
            atomicAdd(&colsq[col], q0);
            atomicAdd(&colsq[col + 1], q1);
        }
    }
    __syncthreads();
    if (tid < 256) { atomicAdd(&d_sum4[tid], colsum[tid]); }
    else if (tid < 512) { atomicAdd(&d_sq4[tid - 256], colsq[tid - 256]); }
}

// ---------------- kernel 4: BN4 + relu + W5 dot -> logits ----------------
__global__ void __launch_bounds__(256) k_final(
    const float* __restrict__ g4, const float* __restrict__ be4,
    const float* __restrict__ W5, const float* __restrict__ b5,
    float* __restrict__ out)
{
    const int lane = threadIdx.x & 31;
    const int wid  = threadIdx.x >> 5;
    float a[8], c[8], w[8];
    #pragma unroll
    for (int j = 0; j < 8; j++) {
        int col = lane * 8 + j;
        float m  = d_sum4[col] * (1.0f / BATCH);
        float v  = d_sq4[col] * (1.0f / BATCH) - m * m;
        float aa = g4[col] * rsqrtf(v + EPS_F);
        a[j] = aa;
        c[j] = be4[col] - aa * m;
        w[j] = W5[col];
    }
    float bias = b5[0];
    for (int i = blockIdx.x * 8 + wid; i < BATCH; i += gridDim.x * 8) {
        uint4 raw = *(const uint4*)(d_yh + (size_t)i * F2DIM + lane * 8);
        float2 f0 = __half22float2(*(__half2*)&raw.x);
        float2 f1 = __half22float2(*(__half2*)&raw.y);
        float2 f2 = __half22float2(*(__half2*)&raw.z);
        float2 f3 = __half22float2(*(__half2*)&raw.w);
        float accv =
            fmaxf(fmaf(a[0], f0.x, c[0]), 0.f) * w[0] +
            fmaxf(fmaf(a[1], f0.y, c[1]), 0.f) * w[1] +
            fmaxf(fmaf(a[2], f1.x, c[2]), 0.f) * w[2] +
            fmaxf(fmaf(a[3], f1.y, c[3]), 0.f) * w[3] +
            fmaxf(fmaf(a[4], f2.x, c[4]), 0.f) * w[4] +
            fmaxf(fmaf(a[5], f2.y, c[5]), 0.f) * w[5] +
            fmaxf(fmaf(a[6], f3.x, c[6]), 0.f) * w[6] +
            fmaxf(fmaf(a[7], f3.y, c[7]), 0.f) * w[7];
        #pragma unroll
        for (int off = 16; off; off >>= 1)
            accv += __shfl_xor_sync(0xffffffffu, accv, off);
        if (lane == 0) out[i] = accv + bias;
    }
}

// ---------------- launch ----------------
extern "C" void kernel_launch(void* const* d_in, const int* in_sizes, int n_in,
                              void* d_out, int out_size)
{
    (void)in_sizes; (void)n_in; (void)out_size;
    const int*   subj  = (const int*)d_in[0];
    const int*   obj   = (const int*)d_in[1];
    const int*   predi = (const int*)d_in[2];
    const float* W1    = (const float*)d_in[3];
    const float* g1    = (const float*)d_in[5];
    const float* be1   = (const float*)d_in[6];
    const float* W2    = (const float*)d_in[7];
    const float* g2    = (const float*)d_in[9];
    const float* be2   = (const float*)d_in[10];
    const float* W3    = (const float*)d_in[11];
    const float* g3    = (const float*)d_in[13];
    const float* be3   = (const float*)d_in[14];
    const float* W4    = (const float*)d_in[15];
    const float* g4    = (const float*)d_in[17];
    const float* be4   = (const float*)d_in[18];
    const float* W5    = (const float*)d_in[19];
    const float* b5    = (const float*)d_in[20];
    float* out = (float*)d_out;

    cudaFuncSetAttribute(k_fused, cudaFuncAttributeMaxDynamicSharedMemorySize, SM_TOT);

    k_zero<<<512, 256>>>(W4);                               // 0
    k_hist<<<BATCH / 256, 256>>>(subj, obj, predi);         // 1
    k_cs<<<1792, 128>>>(W1, W2, W3, 864, 1728);             // 2
    k_fused<<<BATCH / F_ROWS, 512, SM_TOT>>>(subj, obj, predi, W1, W2, W3,
                                             g1, be1, g2, be2, g3, be3);   // 3 <- profile target
    k_final<<<2048, 256>>>(g4, be4, W5, b5, out);           // 4
}